// round 12
// baseline (speedup 1.0000x reference)
#include <cuda_runtime.h>
#include <cuda_fp16.h>
#include <cstdint>

#define T_TOK 16384
#define NE 8
#define NK 2

// ---------------- scratch (device globals; no allocation allowed) ----------------
__device__ int   g_maskmode;
__device__ int   g_cnt[3][16];
__device__ int   g_tok[3][16][T_TOK];
__device__ float g_wgt[3][16][T_TOK];
__device__ uint32_t g_xr [T_TOK * 512 / 2];    // fp16-rounded x (packed half2)
__device__ float g_h1a[T_TOK * 256];           // slot0 partial fp32
__device__ float g_h1b[T_TOK * 256];           // slot1 partial fp32
__device__ uint32_t g_h1s[T_TOK * 256 / 2];    // fp16(h1a+h1b)
__device__ float g_h2a[T_TOK * 256];
__device__ float g_h2b[T_TOK * 256];
__device__ uint32_t g_h2s[T_TOK * 256 / 2];
__device__ float g_h3a[T_TOK * 512];
__device__ float g_h3b[T_TOK * 512];
// combine flags: one word per (token, 32-col group), bits = l3 of the quad
__device__ uint32_t g_f1[T_TOK * 8];           // 256/32
__device__ uint32_t g_f2[T_TOK * 8];
__device__ uint32_t g_f3[T_TOK * 16];          // 512/32
// fragment-ordered fp16 weights: [e][gs(IN/16)][ntp(OUT/16)][lane32][uint4]
__device__ uint4 g_wf1[NE * 32 * 16 * 32];     // stage0: IN=512, OUT=256
__device__ uint4 g_wf2[NE * 16 * 16 * 32];     // stage1: IN=256, OUT=256
__device__ uint4 g_wf3[NE * 16 * 32 * 32];     // stage2: IN=256, OUT=512

// ---------------- helpers ----------------
__device__ __forceinline__ uint32_t pack2(float a, float b) {
    __half2 h = __floats2half2_rn(a, b);
    return *(uint32_t*)&h;
}

__device__ __forceinline__ void mma16(float* c, const uint32_t* a,
                                      uint32_t b0, uint32_t b1) {
    asm volatile(
        "mma.sync.aligned.m16n8k16.row.col.f32.f16.f16.f32 "
        "{%0,%1,%2,%3}, {%4,%5,%6,%7}, {%8,%9}, {%0,%1,%2,%3};"
        : "+f"(c[0]), "+f"(c[1]), "+f"(c[2]), "+f"(c[3])
        : "r"(a[0]), "r"(a[1]), "r"(a[2]), "r"(a[3]), "r"(b0), "r"(b1));
}

__device__ __forceinline__ void cp16(uint32_t smem_dst, const void* gsrc) {
    asm volatile("cp.async.cg.shared.global [%0], [%1], 16;"
                 :: "r"(smem_dst), "l"(gsrc));
}

// ---------------- weight pre-transform (fp16 m16n8k16 B fragments) ----------------
template <int IN, int OUT>
__device__ __forceinline__ void prep_one(int idx, const float* W, uint4* WF) {
    constexpr int NTPP = OUT / 16;
    constexpr int GS   = IN / 16;
    int lane = idx & 31;
    int rest = idx >> 5;
    int ntp  = rest % NTPP;
    int gs   = (rest / NTPP) % GS;
    int e    = rest / (NTPP * GS);
    int n0 = ntp * 16 + (lane >> 2);
    int k0 = gs * 16 + (lane & 3) * 2;
    const float* We = W + (size_t)e * OUT * IN;
    uint4 v;
    v.x = pack2(We[(size_t)(n0 + 0) * IN + k0],     We[(size_t)(n0 + 0) * IN + k0 + 1]);
    v.y = pack2(We[(size_t)(n0 + 0) * IN + k0 + 8], We[(size_t)(n0 + 0) * IN + k0 + 9]);
    v.z = pack2(We[(size_t)(n0 + 8) * IN + k0],     We[(size_t)(n0 + 8) * IN + k0 + 1]);
    v.w = pack2(We[(size_t)(n0 + 8) * IN + k0 + 8], We[(size_t)(n0 + 8) * IN + k0 + 9]);
    WF[idx] = v;
}

// ---------------- mask dtype detection + counter zeroing ----------------
__global__ void detect_and_zero(const unsigned char* __restrict__ m) {
    __shared__ int bad;
    if (threadIdx.x == 0) bad = 0;
    if (threadIdx.x < 48) ((int*)g_cnt)[threadIdx.x] = 0;
    __syncthreads();
    int t = threadIdx.x;
    #pragma unroll
    for (int k = 0; k < NK; k++) {
        int s = 0;
        #pragma unroll
        for (int e = 0; e < NE; e++)
            s += (m[(e * NK + k) * T_TOK + t] != 0) ? 1 : 0;
        if (s != 1) bad = 1;
    }
    __syncthreads();
    if (threadIdx.x == 0) g_maskmode = bad ? 0 : 1;
}

// ---------------- fused pre-pass: zero flags + route + prep + round_x ----------------
#define NZ_U4   131072          // 512K flag words / 4
#define NROUTE  (3 * NK * T_TOK)
#define NPREP   (NE*32*16*32 + NE*16*16*32 + NE*16*32*32)
#define NRX     (T_TOK * 512 / 8)      // one uint4 (8 halves) per thread
#define PRE_THREADS (NZ_U4 + NROUTE + NPREP + NRX)

__global__ void pre_fused(const unsigned char* __restrict__ m1,
                          const unsigned char* __restrict__ m2,
                          const unsigned char* __restrict__ m3,
                          const float* __restrict__ r1,
                          const float* __restrict__ r2,
                          const float* __restrict__ r3,
                          const float* __restrict__ W1,
                          const float* __restrict__ W2,
                          const float* __restrict__ W3,
                          const float4* __restrict__ x) {
    int idx = blockIdx.x * blockDim.x + threadIdx.x;
    // ---- zero flags (uint4 granularity) ----
    if (idx < NZ_U4) {
        uint4 z = {0, 0, 0, 0};
        if (idx < 32768)       ((uint4*)g_f1)[idx] = z;
        else if (idx < 65536)  ((uint4*)g_f2)[idx - 32768] = z;
        else                   ((uint4*)g_f3)[idx - 65536] = z;
        return;
    }
    idx -= NZ_U4;
    // ---- routing ----
    if (idx < NROUTE) {
        int s   = idx / (NK * T_TOK);
        int rem = idx % (NK * T_TOK);
        int k   = rem / T_TOK;
        int t   = rem % T_TOK;
        const unsigned char* m = (s == 0) ? m1 : (s == 1) ? m2 : m3;
        const float*         r = (s == 0) ? r1 : (s == 1) ? r2 : r3;
        int e = 0;
        if (g_maskmode) {
            #pragma unroll
            for (int i = 0; i < NE; i++)
                if (m[(i * NK + k) * T_TOK + t]) e = i;
        } else {
            const int* mi = (const int*)m;
            #pragma unroll
            for (int i = 0; i < NE; i++)
                if (mi[(i * NK + k) * T_TOK + t]) e = i;
        }
        float w = r[t * NK + k];
        int gg = k * NE + e;
        int p = atomicAdd(&g_cnt[s][gg], 1);
        g_tok[s][gg][p] = t;
        g_wgt[s][gg][p] = w;
        return;
    }
    idx -= NROUTE;
    // ---- weight prep ----
    if (idx < NPREP) {
        constexpr int N1 = NE * 32 * 16 * 32;
        constexpr int N2 = NE * 16 * 16 * 32;
        if (idx < N1)            { prep_one<512, 256>(idx, W1, g_wf1); }
        else if (idx < N1 + N2)  { prep_one<256, 256>(idx - N1, W2, g_wf2); }
        else                     { prep_one<256, 512>(idx - N1 - N2, W3, g_wf3); }
        return;
    }
    idx -= NPREP;
    // ---- round x to fp16 (one uint4 = 8 floats per thread) ----
    if (idx < NRX) {
        float4 v0 = x[2 * idx], v1 = x[2 * idx + 1];
        uint4 u = { pack2(v0.x, v0.y), pack2(v0.z, v0.w),
                    pack2(v1.x, v1.y), pack2(v1.z, v1.w) };
        ((uint4*)g_xr)[idx] = u;
    }
}

// ---------------- fp16 mma.sync gathered expert GEMM, flag-fused combine ----------------
// BM=128, BN=128, BK=64 (4 k16 steps), 256 threads, 8 warps (2m x 4n), warp 64x32.
// Epilogue: store my slot's weighted partial (fp32); fence; atomicOr flag; if my bit
// was set, partner finished first -> I combine: read other, add, emit
// (fp16-pack for stages 0/1, final relu fp32->out for stage 2).
#define SMEM_TOTAL_BYTES 99328

template <int STAGE, int IN, int OUT>
__global__ __launch_bounds__(256, 2)
void moe_mma(const void* __restrict__ Ain,
             const float* __restrict__ Bias,
             float* __restrict__ OutF) {
    const uint4* WFg;
    float *Pa, *Pb;
    uint32_t *Flags, *PackDst;
    if constexpr (STAGE == 0)      { WFg = g_wf1; Pa = g_h1a; Pb = g_h1b; Flags = g_f1; PackDst = g_h1s; }
    else if constexpr (STAGE == 1) { WFg = g_wf2; Pa = g_h2a; Pb = g_h2b; Flags = g_f2; PackDst = g_h2s; }
    else                           { WFg = g_wf3; Pa = g_h3a; Pb = g_h3b; Flags = g_f3; PackDst = nullptr; }
    constexpr bool RELU = (STAGE == 2);
    constexpr int NTPP = OUT / 16;
    constexpr int GS   = IN / 16;
    constexpr int NC   = IN / 64;
    constexpr int OW   = OUT / 32;     // flag words per token

    const int g  = blockIdx.z;                 // slot*8 + expert
    const int n  = g_cnt[STAGE][g];
    const int m0 = blockIdx.x * 128;
    if (m0 >= n) return;
    const int e  = g & 7;
    const int n0 = blockIdx.y * 128;
    const int slot = g >> 3;
    float*       My    = slot ? Pb : Pa;
    const float* Other = slot ? Pa : Pb;

    extern __shared__ __align__(16) char dsm[];
    int*   s_tok = (int*)(dsm + 98304);
    float* s_w   = (float*)(dsm + 98816);

    const int tid  = threadIdx.x;
    const int wid  = tid >> 5;
    const int lane = tid & 31;
    const int wm   = wid >> 2;
    const int wn   = wid & 3;
    const int l2   = lane >> 2;
    const int l3   = lane & 3;

    if (tid < 128) {
        int gi  = m0 + tid;
        int src = (gi < n) ? gi : (n - 1);
        s_tok[tid] = g_tok[STAGE][g][src];
        s_w[tid]   = (gi < n) ? g_wgt[STAGE][g][src] : 0.0f;
    }
    __syncthreads();

    const uint4* WFe = WFg + (size_t)e * GS * NTPP * 32;
    const int ntp0 = blockIdx.y * 8;

    // A copy plan: rows (tid>>3)+{0,32,64,96}, 16B segment tid&7
    const int aseg = tid & 7;
    const int dseg = aseg ^ ((tid >> 3) & 7);
    const char* abase[4];
    uint32_t adst[4];
    uint32_t smA = (uint32_t)__cvta_generic_to_shared(dsm);
    #pragma unroll
    for (int i = 0; i < 4; i++) {
        int row = (tid >> 3) + i * 32;
        abase[i] = (const char*)Ain + ((size_t)s_tok[row] * IN + aseg * 8) * 2;
        adst[i]  = smA + row * 128 + dseg * 16;
    }
    uint32_t smB = (uint32_t)__cvta_generic_to_shared(dsm + 49152);

    auto ISSUE = [&](int ch, int buf) {
        #pragma unroll
        for (int i = 0; i < 4; i++)
            cp16(adst[i] + buf * 16384, abase[i] + ch * 128);
        #pragma unroll
        for (int i = 0; i < 4; i++) {
            int f  = tid + i * 256;           // [s4][ntp8][lane32]
            int bs = f >> 8;
            int bp = (f >> 5) & 7;
            int bl = f & 31;
            cp16(smB + buf * 16384 + f * 16,
                 WFe + ((size_t)(ch * 4 + bs) * NTPP + ntp0 + bp) * 32 + bl);
        }
        asm volatile("cp.async.commit_group;" ::: "memory");
    };

    float c[4][4][4];
    #pragma unroll
    for (int a = 0; a < 4; a++)
        #pragma unroll
        for (int b = 0; b < 4; b++)
            #pragma unroll
            for (int d = 0; d < 4; d++) c[a][b][d] = 0.0f;

    auto COMP = [&](int buf) {
        const char* Ab = dsm + buf * 16384;
        const uint4* Bb = (const uint4*)(dsm + 49152 + buf * 16384);
        #pragma unroll
        for (int s = 0; s < 4; s++) {
            const int off0 = (((2 * s)     ^ l2) << 4) + l3 * 4;
            const int off1 = (((2 * s + 1) ^ l2) << 4) + l3 * 4;
            uint32_t a[4][4];
            #pragma unroll
            for (int mi = 0; mi < 4; mi++) {
                const char* rp = Ab + (wm * 64 + mi * 16 + l2) * 128;
                a[mi][0] = *(const uint32_t*)(rp + off0);
                a[mi][1] = *(const uint32_t*)(rp + 1024 + off0);
                a[mi][2] = *(const uint32_t*)(rp + off1);
                a[mi][3] = *(const uint32_t*)(rp + 1024 + off1);
            }
            uint4 b0 = Bb[s * 256 + (wn * 2 + 0) * 32 + lane];
            uint4 b1 = Bb[s * 256 + (wn * 2 + 1) * 32 + lane];
            #pragma unroll
            for (int mi = 0; mi < 4; mi++) {
                mma16(c[mi][0], a[mi], b0.x, b0.y);
                mma16(c[mi][1], a[mi], b0.z, b0.w);
                mma16(c[mi][2], a[mi], b1.x, b1.y);
                mma16(c[mi][3], a[mi], b1.z, b1.w);
            }
        }
    };

    // 3-deep pipeline
    ISSUE(0, 0);
    ISSUE(1, 1);
    asm volatile("cp.async.wait_group 1;" ::: "memory");
    __syncthreads();
    int buf = 0;
    for (int ch = 0; ch < NC; ch++) {
        COMP(buf);
        if (ch + 2 < NC) {
            int nb = buf + 2; if (nb >= 3) nb -= 3;
            ISSUE(ch + 2, nb);
            asm volatile("cp.async.wait_group 1;" ::: "memory");
            __syncthreads();
        } else if (ch + 1 < NC) {
            asm volatile("cp.async.wait_group 0;" ::: "memory");
            __syncthreads();
        }
        if (++buf == 3) buf = 0;
    }

    // --- epilogue ---
    float2 bias[4];
    #pragma unroll
    for (int nt = 0; nt < 4; nt++)
        bias[nt] = *(const float2*)&Bias[e * OUT + n0 + wn * 32 + nt * 8 + l3 * 2];

    // pass A: store my weighted partials
    #pragma unroll
    for (int mi = 0; mi < 4; mi++) {
        #pragma unroll
        for (int half = 0; half < 2; half++) {
            int r  = wm * 64 + mi * 16 + l2 + half * 8;
            int gi = m0 + r;
            if (gi >= n) continue;
            int   t = s_tok[r];
            float w = s_w[r];
            #pragma unroll
            for (int nt = 0; nt < 4; nt++) {
                float2 v;
                v.x = c[mi][nt][half * 2 + 0] + bias[nt].x;
                v.y = c[mi][nt][half * 2 + 1] + bias[nt].y;
                if constexpr (RELU) { v.x = fmaxf(v.x, 0.0f); v.y = fmaxf(v.y, 0.0f); }
                v.x *= w; v.y *= w;
                *(float2*)&My[(size_t)t * OUT + n0 + wn * 32 + nt * 8 + l3 * 2] = v;
            }
        }
    }
    __threadfence();   // my partials visible before flags

    // pass B: flag; detect second-arrival per row
    uint32_t sec = 0;
    #pragma unroll
    for (int mi = 0; mi < 4; mi++) {
        #pragma unroll
        for (int half = 0; half < 2; half++) {
            int r  = wm * 64 + mi * 16 + l2 + half * 8;
            int gi = m0 + r;
            if (gi >= n) continue;
            int t = s_tok[r];
            uint32_t old = atomicOr(&Flags[t * OW + (n0 >> 5) + wn], 1u << l3);
            if ((old >> l3) & 1) sec |= 1u << (mi * 2 + half);
        }
    }
    if (sec) {
        __threadfence();   // acquire: partner's partials visible
        #pragma unroll
        for (int mi = 0; mi < 4; mi++) {
            #pragma unroll
            for (int half = 0; half < 2; half++) {
                if (!((sec >> (mi * 2 + half)) & 1)) continue;
                int r = wm * 64 + mi * 16 + l2 + half * 8;
                int   t = s_tok[r];
                float w = s_w[r];
                #pragma unroll
                for (int nt = 0; nt < 4; nt++) {
                    size_t idx = (size_t)t * OUT + n0 + wn * 32 + nt * 8 + l3 * 2;
                    float2 v;
                    v.x = c[mi][nt][half * 2 + 0] + bias[nt].x;
                    v.y = c[mi][nt][half * 2 + 1] + bias[nt].y;
                    if constexpr (RELU) { v.x = fmaxf(v.x, 0.0f); v.y = fmaxf(v.y, 0.0f); }
                    v.x *= w; v.y *= w;
                    float2 p = *(const float2*)&Other[idx];
                    v.x += p.x; v.y += p.y;
                    if constexpr (STAGE < 2) {
                        PackDst[idx >> 1] = pack2(v.x, v.y);
                    } else {
                        float2 o;
                        o.x = fmaxf(v.x, 0.0f);
                        o.y = fmaxf(v.y, 0.0f);
                        *(float2*)&OutF[idx] = o;
                    }
                }
            }
        }
    }
}

// ---------------- launch ----------------
extern "C" void kernel_launch(void* const* d_in, const int* in_sizes, int n_in,
                              void* d_out, int out_size) {
    const float*         x  = (const float*)d_in[0];
    const unsigned char* m1 = (const unsigned char*)d_in[1];
    const unsigned char* m2 = (const unsigned char*)d_in[2];
    const unsigned char* m3 = (const unsigned char*)d_in[3];
    const float*         r1 = (const float*)d_in[4];
    const float*         r2 = (const float*)d_in[5];
    const float*         r3 = (const float*)d_in[6];
    const float*         W1 = (const float*)d_in[7];
    const float*         b1 = (const float*)d_in[8];
    const float*         W2 = (const float*)d_in[9];
    const float*         b2 = (const float*)d_in[10];
    const float*         W3 = (const float*)d_in[11];
    const float*         b3 = (const float*)d_in[12];
    float* out = (float*)d_out;

    void *xr, *h1s, *h2s;
    cudaGetSymbolAddress(&xr,  g_xr);
    cudaGetSymbolAddress(&h1s, g_h1s);
    cudaGetSymbolAddress(&h2s, g_h2s);

    static bool attr_done = false;
    if (!attr_done) {
        cudaFuncSetAttribute(moe_mma<0, 512, 256>,
                             cudaFuncAttributeMaxDynamicSharedMemorySize, SMEM_TOTAL_BYTES);
        cudaFuncSetAttribute(moe_mma<1, 256, 256>,
                             cudaFuncAttributeMaxDynamicSharedMemorySize, SMEM_TOTAL_BYTES);
        cudaFuncSetAttribute(moe_mma<2, 256, 512>,
                             cudaFuncAttributeMaxDynamicSharedMemorySize, SMEM_TOTAL_BYTES);
        attr_done = true;
    }

    detect_and_zero<<<1, 256>>>(m1);
    pre_fused<<<(PRE_THREADS + 255) / 256, 256>>>(m1, m2, m3, r1, r2, r3,
                                                  W1, W2, W3, (const float4*)x);

    dim3 g1(T_TOK / 128, 256 / 128, 16);
    dim3 g3(T_TOK / 128, 512 / 128, 16);

    moe_mma<0, 512, 256><<<g1, 256, SMEM_TOTAL_BYTES>>>(xr, b1, nullptr);
    moe_mma<1, 256, 256><<<g1, 256, SMEM_TOTAL_BYTES>>>(h1s, b2, nullptr);
    moe_mma<2, 256, 512><<<g3, 256, SMEM_TOTAL_BYTES>>>(h2s, b3, out);
}

// round 13
// speedup vs baseline: 1.5422x; 1.5422x over previous
#include <cuda_runtime.h>
#include <cuda_fp16.h>
#include <cstdint>

#define T_TOK 16384
#define NE 8
#define NK 2

// ---------------- scratch (device globals; no allocation allowed) ----------------
__device__ int   g_maskmode;
__device__ int   g_cnt[3][16];
__device__ int   g_tok[3][16][T_TOK];
__device__ float g_wgt[3][16][T_TOK];
__device__ uint32_t g_xr [T_TOK * 512 / 2];    // fp16-rounded x (packed half2)
__device__ float g_h1a[T_TOK * 256];           // stage0 slot partials fp32
__device__ float g_h1b[T_TOK * 256];
__device__ uint32_t g_h1s[T_TOK * 256 / 2];    // fp16(h1a+h1b)
__device__ float g_h2a[T_TOK * 256];
__device__ float g_h2b[T_TOK * 256];
__device__ uint32_t g_h2s[T_TOK * 256 / 2];
__device__ uint32_t g_h3a[T_TOK * 512 / 2];    // stage2 slot partials, packed fp16
__device__ uint32_t g_h3b[T_TOK * 512 / 2];
// fragment-ordered fp16 weights: [e][gs(IN/16)][ntp(OUT/16)][lane32][uint4]
__device__ uint4 g_wf1[NE * 32 * 16 * 32];     // stage0: IN=512, OUT=256
__device__ uint4 g_wf2[NE * 16 * 16 * 32];     // stage1: IN=256, OUT=256
__device__ uint4 g_wf3[NE * 16 * 32 * 32];     // stage2: IN=256, OUT=512

// ---------------- helpers ----------------
__device__ __forceinline__ uint32_t pack2(float a, float b) {
    __half2 h = __floats2half2_rn(a, b);
    return *(uint32_t*)&h;
}

__device__ __forceinline__ void mma16(float* c, const uint32_t* a,
                                      uint32_t b0, uint32_t b1) {
    asm volatile(
        "mma.sync.aligned.m16n8k16.row.col.f32.f16.f16.f32 "
        "{%0,%1,%2,%3}, {%4,%5,%6,%7}, {%8,%9}, {%0,%1,%2,%3};"
        : "+f"(c[0]), "+f"(c[1]), "+f"(c[2]), "+f"(c[3])
        : "r"(a[0]), "r"(a[1]), "r"(a[2]), "r"(a[3]), "r"(b0), "r"(b1));
}

__device__ __forceinline__ void cp16(uint32_t smem_dst, const void* gsrc) {
    asm volatile("cp.async.cg.shared.global [%0], [%1], 16;"
                 :: "r"(smem_dst), "l"(gsrc));
}

// ---------------- weight pre-transform (fp16 m16n8k16 B fragments) ----------------
template <int IN, int OUT>
__device__ __forceinline__ void prep_one(int idx, const float* W, uint4* WF) {
    constexpr int NTPP = OUT / 16;
    constexpr int GS   = IN / 16;
    int lane = idx & 31;
    int rest = idx >> 5;
    int ntp  = rest % NTPP;
    int gs   = (rest / NTPP) % GS;
    int e    = rest / (NTPP * GS);
    int n0 = ntp * 16 + (lane >> 2);
    int k0 = gs * 16 + (lane & 3) * 2;
    const float* We = W + (size_t)e * OUT * IN;
    uint4 v;
    v.x = pack2(We[(size_t)(n0 + 0) * IN + k0],     We[(size_t)(n0 + 0) * IN + k0 + 1]);
    v.y = pack2(We[(size_t)(n0 + 0) * IN + k0 + 8], We[(size_t)(n0 + 0) * IN + k0 + 9]);
    v.z = pack2(We[(size_t)(n0 + 8) * IN + k0],     We[(size_t)(n0 + 8) * IN + k0 + 1]);
    v.w = pack2(We[(size_t)(n0 + 8) * IN + k0 + 8], We[(size_t)(n0 + 8) * IN + k0 + 9]);
    WF[idx] = v;
}

// ---------------- mask dtype detection + counter zeroing ----------------
__global__ void detect_and_zero(const unsigned char* __restrict__ m) {
    __shared__ int bad;
    if (threadIdx.x == 0) bad = 0;
    if (threadIdx.x < 48) ((int*)g_cnt)[threadIdx.x] = 0;
    __syncthreads();
    int t = threadIdx.x;
    #pragma unroll
    for (int k = 0; k < NK; k++) {
        int s = 0;
        #pragma unroll
        for (int e = 0; e < NE; e++)
            s += (m[(e * NK + k) * T_TOK + t] != 0) ? 1 : 0;
        if (s != 1) bad = 1;
    }
    __syncthreads();
    if (threadIdx.x == 0) g_maskmode = bad ? 0 : 1;
}

// ---------------- fused pre-pass: route + prep + round_x ----------------
#define NROUTE  (3 * NK * T_TOK)
#define NPREP   (NE*32*16*32 + NE*16*16*32 + NE*16*32*32)
#define NRX     (T_TOK * 512 / 8)      // one uint4 (8 halves) per thread
#define PRE_THREADS (NROUTE + NPREP + NRX)

__global__ void pre_fused(const unsigned char* __restrict__ m1,
                          const unsigned char* __restrict__ m2,
                          const unsigned char* __restrict__ m3,
                          const float* __restrict__ r1,
                          const float* __restrict__ r2,
                          const float* __restrict__ r3,
                          const float* __restrict__ W1,
                          const float* __restrict__ W2,
                          const float* __restrict__ W3,
                          const float4* __restrict__ x) {
    int idx = blockIdx.x * blockDim.x + threadIdx.x;
    // ---- routing ----
    if (idx < NROUTE) {
        int s   = idx / (NK * T_TOK);
        int rem = idx % (NK * T_TOK);
        int k   = rem / T_TOK;
        int t   = rem % T_TOK;
        const unsigned char* m = (s == 0) ? m1 : (s == 1) ? m2 : m3;
        const float*         r = (s == 0) ? r1 : (s == 1) ? r2 : r3;
        int e = 0;
        if (g_maskmode) {
            #pragma unroll
            for (int i = 0; i < NE; i++)
                if (m[(i * NK + k) * T_TOK + t]) e = i;
        } else {
            const int* mi = (const int*)m;
            #pragma unroll
            for (int i = 0; i < NE; i++)
                if (mi[(i * NK + k) * T_TOK + t]) e = i;
        }
        float w = r[t * NK + k];
        int gg = k * NE + e;
        int p = atomicAdd(&g_cnt[s][gg], 1);
        g_tok[s][gg][p] = t;
        g_wgt[s][gg][p] = w;
        return;
    }
    idx -= NROUTE;
    // ---- weight prep ----
    if (idx < NPREP) {
        constexpr int N1 = NE * 32 * 16 * 32;
        constexpr int N2 = NE * 16 * 16 * 32;
        if (idx < N1)            { prep_one<512, 256>(idx, W1, g_wf1); }
        else if (idx < N1 + N2)  { prep_one<256, 256>(idx - N1, W2, g_wf2); }
        else                     { prep_one<256, 512>(idx - N1 - N2, W3, g_wf3); }
        return;
    }
    idx -= NPREP;
    // ---- round x to fp16 (one uint4 = 8 floats per thread) ----
    if (idx < NRX) {
        float4 v0 = x[2 * idx], v1 = x[2 * idx + 1];
        uint4 u = { pack2(v0.x, v0.y), pack2(v0.z, v0.w),
                    pack2(v1.x, v1.y), pack2(v1.z, v1.w) };
        ((uint4*)g_xr)[idx] = u;
    }
}

// ---------------- activation summing (fp32 partials -> fp16 packed) ----------------
__global__ void sum_round(const float4* __restrict__ a, const float4* __restrict__ b,
                          uint4* __restrict__ dst) {
    int i = blockIdx.x * blockDim.x + threadIdx.x;
    float4 a0 = a[2 * i], a1 = a[2 * i + 1];
    float4 b0 = b[2 * i], b1 = b[2 * i + 1];
    uint4 u = { pack2(a0.x + b0.x, a0.y + b0.y), pack2(a0.z + b0.z, a0.w + b0.w),
                pack2(a1.x + b1.x, a1.y + b1.y), pack2(a1.z + b1.z, a1.w + b1.w) };
    dst[i] = u;
}

// ---------------- fp16 mma.sync gathered expert GEMM ----------------
// BM=128, BN=128, BK=64 (4 k16 steps), 256 threads, 8 warps (2m x 4n), warp 64x32.
// A: pre-rounded fp16 via cp.async, 16B-XOR swizzle; B: cp.async fragment gmem.
// 3-deep pipeline, 1 sync/chunk. STAGE<2: fp32 partial out; STAGE==2: packed fp16 out.
#define SMEM_TOTAL_BYTES 99328

template <int STAGE, int IN, int OUT>
__global__ __launch_bounds__(256, 2)
void moe_mma(const void* __restrict__ Ain,
             const float* __restrict__ Bias) {
    const uint4* WFg;
    void *O0, *O1;
    if constexpr (STAGE == 0)      { WFg = g_wf1; O0 = g_h1a; O1 = g_h1b; }
    else if constexpr (STAGE == 1) { WFg = g_wf2; O0 = g_h2a; O1 = g_h2b; }
    else                           { WFg = g_wf3; O0 = g_h3a; O1 = g_h3b; }
    constexpr bool RELU = (STAGE == 2);
    constexpr int NTPP = OUT / 16;
    constexpr int GS   = IN / 16;
    constexpr int NC   = IN / 64;

    const int g  = blockIdx.z;                 // slot*8 + expert
    const int n  = g_cnt[STAGE][g];
    const int m0 = blockIdx.x * 128;
    if (m0 >= n) return;
    const int e  = g & 7;
    const int n0 = blockIdx.y * 128;
    void* Out = (g >= 8) ? O1 : O0;

    extern __shared__ __align__(16) char dsm[];
    int*   s_tok = (int*)(dsm + 98304);
    float* s_w   = (float*)(dsm + 98816);

    const int tid  = threadIdx.x;
    const int wid  = tid >> 5;
    const int lane = tid & 31;
    const int wm   = wid >> 2;
    const int wn   = wid & 3;
    const int l2   = lane >> 2;
    const int l3   = lane & 3;

    if (tid < 128) {
        int gi  = m0 + tid;
        int src = (gi < n) ? gi : (n - 1);
        s_tok[tid] = g_tok[STAGE][g][src];
        s_w[tid]   = (gi < n) ? g_wgt[STAGE][g][src] : 0.0f;
    }
    __syncthreads();

    const uint4* WFe = WFg + (size_t)e * GS * NTPP * 32;
    const int ntp0 = blockIdx.y * 8;

    // A copy plan: rows (tid>>3)+{0,32,64,96}, 16B segment tid&7
    const int aseg = tid & 7;
    const int dseg = aseg ^ ((tid >> 3) & 7);
    const char* abase[4];
    uint32_t adst[4];
    uint32_t smA = (uint32_t)__cvta_generic_to_shared(dsm);
    #pragma unroll
    for (int i = 0; i < 4; i++) {
        int row = (tid >> 3) + i * 32;
        abase[i] = (const char*)Ain + ((size_t)s_tok[row] * IN + aseg * 8) * 2;
        adst[i]  = smA + row * 128 + dseg * 16;
    }
    uint32_t smB = (uint32_t)__cvta_generic_to_shared(dsm + 49152);

    auto ISSUE = [&](int ch, int buf) {
        #pragma unroll
        for (int i = 0; i < 4; i++)
            cp16(adst[i] + buf * 16384, abase[i] + ch * 128);
        #pragma unroll
        for (int i = 0; i < 4; i++) {
            int f  = tid + i * 256;           // [s4][ntp8][lane32]
            int bs = f >> 8;
            int bp = (f >> 5) & 7;
            int bl = f & 31;
            cp16(smB + buf * 16384 + f * 16,
                 WFe + ((size_t)(ch * 4 + bs) * NTPP + ntp0 + bp) * 32 + bl);
        }
        asm volatile("cp.async.commit_group;" ::: "memory");
    };

    float c[4][4][4];
    #pragma unroll
    for (int a = 0; a < 4; a++)
        #pragma unroll
        for (int b = 0; b < 4; b++)
            #pragma unroll
            for (int d = 0; d < 4; d++) c[a][b][d] = 0.0f;

    auto COMP = [&](int buf) {
        const char* Ab = dsm + buf * 16384;
        const uint4* Bb = (const uint4*)(dsm + 49152 + buf * 16384);
        #pragma unroll
        for (int s = 0; s < 4; s++) {
            const int off0 = (((2 * s)     ^ l2) << 4) + l3 * 4;
            const int off1 = (((2 * s + 1) ^ l2) << 4) + l3 * 4;
            uint32_t a[4][4];
            #pragma unroll
            for (int mi = 0; mi < 4; mi++) {
                const char* rp = Ab + (wm * 64 + mi * 16 + l2) * 128;
                a[mi][0] = *(const uint32_t*)(rp + off0);
                a[mi][1] = *(const uint32_t*)(rp + 1024 + off0);
                a[mi][2] = *(const uint32_t*)(rp + off1);
                a[mi][3] = *(const uint32_t*)(rp + 1024 + off1);
            }
            uint4 b0 = Bb[s * 256 + (wn * 2 + 0) * 32 + lane];
            uint4 b1 = Bb[s * 256 + (wn * 2 + 1) * 32 + lane];
            #pragma unroll
            for (int mi = 0; mi < 4; mi++) {
                mma16(c[mi][0], a[mi], b0.x, b0.y);
                mma16(c[mi][1], a[mi], b0.z, b0.w);
                mma16(c[mi][2], a[mi], b1.x, b1.y);
                mma16(c[mi][3], a[mi], b1.z, b1.w);
            }
        }
    };

    // 3-deep pipeline
    ISSUE(0, 0);
    ISSUE(1, 1);
    asm volatile("cp.async.wait_group 1;" ::: "memory");
    __syncthreads();
    int buf = 0;
    for (int ch = 0; ch < NC; ch++) {
        COMP(buf);
        if (ch + 2 < NC) {
            int nb = buf + 2; if (nb >= 3) nb -= 3;
            ISSUE(ch + 2, nb);
            asm volatile("cp.async.wait_group 1;" ::: "memory");
            __syncthreads();
        } else if (ch + 1 < NC) {
            asm volatile("cp.async.wait_group 0;" ::: "memory");
            __syncthreads();
        }
        if (++buf == 3) buf = 0;
    }

    // --- epilogue: bias (+relu) * routing weight, scatter by token ---
    float2 bias[4];
    #pragma unroll
    for (int nt = 0; nt < 4; nt++)
        bias[nt] = *(const float2*)&Bias[e * OUT + n0 + wn * 32 + nt * 8 + l3 * 2];

    #pragma unroll
    for (int mi = 0; mi < 4; mi++) {
        #pragma unroll
        for (int half = 0; half < 2; half++) {
            int r  = wm * 64 + mi * 16 + l2 + half * 8;
            int gi = m0 + r;
            if (gi >= n) continue;
            int   t = s_tok[r];
            float w = s_w[r];
            #pragma unroll
            for (int nt = 0; nt < 4; nt++) {
                size_t idx = (size_t)t * OUT + n0 + wn * 32 + nt * 8 + l3 * 2;
                float2 v;
                v.x = c[mi][nt][half * 2 + 0] + bias[nt].x;
                v.y = c[mi][nt][half * 2 + 1] + bias[nt].y;
                if constexpr (RELU) {
                    v.x = fmaxf(v.x, 0.0f);
                    v.y = fmaxf(v.y, 0.0f);
                }
                v.x *= w; v.y *= w;
                if constexpr (STAGE < 2) {
                    *(float2*)&((float*)Out)[idx] = v;
                } else {
                    ((uint32_t*)Out)[idx >> 1] = pack2(v.x, v.y);
                }
            }
        }
    }
}

// ---------------- final combine + relu (reads packed fp16 partials) ----------------
__global__ void finalize(float* __restrict__ out) {
    int i = blockIdx.x * blockDim.x + threadIdx.x;   // one uint4 (8 halves) per thread
    uint4 ua = ((const uint4*)g_h3a)[i];
    uint4 ub = ((const uint4*)g_h3b)[i];
    float4 o0, o1;
    {
        float2 a = __half22float2(*(__half2*)&ua.x), b = __half22float2(*(__half2*)&ub.x);
        o0.x = fmaxf(a.x + b.x, 0.0f); o0.y = fmaxf(a.y + b.y, 0.0f);
        a = __half22float2(*(__half2*)&ua.y); b = __half22float2(*(__half2*)&ub.y);
        o0.z = fmaxf(a.x + b.x, 0.0f); o0.w = fmaxf(a.y + b.y, 0.0f);
        a = __half22float2(*(__half2*)&ua.z); b = __half22float2(*(__half2*)&ub.z);
        o1.x = fmaxf(a.x + b.x, 0.0f); o1.y = fmaxf(a.y + b.y, 0.0f);
        a = __half22float2(*(__half2*)&ua.w); b = __half22float2(*(__half2*)&ub.w);
        o1.z = fmaxf(a.x + b.x, 0.0f); o1.w = fmaxf(a.y + b.y, 0.0f);
    }
    ((float4*)out)[2 * i]     = o0;
    ((float4*)out)[2 * i + 1] = o1;
}

// ---------------- launch ----------------
extern "C" void kernel_launch(void* const* d_in, const int* in_sizes, int n_in,
                              void* d_out, int out_size) {
    const float*         x  = (const float*)d_in[0];
    const unsigned char* m1 = (const unsigned char*)d_in[1];
    const unsigned char* m2 = (const unsigned char*)d_in[2];
    const unsigned char* m3 = (const unsigned char*)d_in[3];
    const float*         r1 = (const float*)d_in[4];
    const float*         r2 = (const float*)d_in[5];
    const float*         r3 = (const float*)d_in[6];
    const float*         W1 = (const float*)d_in[7];
    const float*         b1 = (const float*)d_in[8];
    const float*         W2 = (const float*)d_in[9];
    const float*         b2 = (const float*)d_in[10];
    const float*         W3 = (const float*)d_in[11];
    const float*         b3 = (const float*)d_in[12];
    float* out = (float*)d_out;

    void *xr, *h1a, *h1b, *h1s, *h2a, *h2b, *h2s;
    cudaGetSymbolAddress(&xr,  g_xr);
    cudaGetSymbolAddress(&h1a, g_h1a);
    cudaGetSymbolAddress(&h1b, g_h1b);
    cudaGetSymbolAddress(&h1s, g_h1s);
    cudaGetSymbolAddress(&h2a, g_h2a);
    cudaGetSymbolAddress(&h2b, g_h2b);
    cudaGetSymbolAddress(&h2s, g_h2s);

    static bool attr_done = false;
    if (!attr_done) {
        cudaFuncSetAttribute(moe_mma<0, 512, 256>,
                             cudaFuncAttributeMaxDynamicSharedMemorySize, SMEM_TOTAL_BYTES);
        cudaFuncSetAttribute(moe_mma<1, 256, 256>,
                             cudaFuncAttributeMaxDynamicSharedMemorySize, SMEM_TOTAL_BYTES);
        cudaFuncSetAttribute(moe_mma<2, 256, 512>,
                             cudaFuncAttributeMaxDynamicSharedMemorySize, SMEM_TOTAL_BYTES);
        attr_done = true;
    }

    detect_and_zero<<<1, 256>>>(m1);
    pre_fused<<<(PRE_THREADS + 255) / 256, 256>>>(m1, m2, m3, r1, r2, r3,
                                                  W1, W2, W3, (const float4*)x);

    dim3 g1(T_TOK / 128, 256 / 128, 16);
    dim3 g3(T_TOK / 128, 512 / 128, 16);

    moe_mma<0, 512, 256><<<g1, 256, SMEM_TOTAL_BYTES>>>(xr, b1);
    sum_round<<<(T_TOK * 256 / 8) / 256, 256>>>((const float4*)h1a, (const float4*)h1b, (uint4*)h1s);
    moe_mma<1, 256, 256><<<g1, 256, SMEM_TOTAL_BYTES>>>(h1s, b2);
    sum_round<<<(T_TOK * 256 / 8) / 256, 256>>>((const float4*)h2a, (const float4*)h2b, (uint4*)h2s);
    moe_mma<2, 256, 512><<<g3, 256, SMEM_TOTAL_BYTES>>>(h2s, b3);

    finalize<<<(T_TOK * 512 / 8) / 256, 256>>>(out);
}

// round 14
// speedup vs baseline: 1.5638x; 1.0140x over previous
#include <cuda_runtime.h>
#include <cuda_fp16.h>
#include <cstdint>

#define T_TOK 16384
#define NE 8
#define NK 2

// ---------------- scratch (device globals; no allocation allowed) ----------------
__device__ int   g_maskmode;
__device__ int   g_cnt[3][16];
__device__ int   g_tok[3][16][T_TOK];
__device__ float g_wgt[3][16][T_TOK];
__device__ uint32_t g_xr [T_TOK * 512 / 2];    // fp16-rounded x (packed half2)
__device__ uint32_t g_h1a[T_TOK * 256 / 2];    // slot partials, packed fp16
__device__ uint32_t g_h1b[T_TOK * 256 / 2];
__device__ uint32_t g_h1s[T_TOK * 256 / 2];    // fp16(h1a+h1b)
__device__ uint32_t g_h2a[T_TOK * 256 / 2];
__device__ uint32_t g_h2b[T_TOK * 256 / 2];
__device__ uint32_t g_h2s[T_TOK * 256 / 2];
__device__ uint32_t g_h3a[T_TOK * 512 / 2];
__device__ uint32_t g_h3b[T_TOK * 512 / 2];
// fragment-ordered fp16 weights: [e][gs(IN/16)][ntp(OUT/16)][lane32][uint4]
__device__ uint4 g_wf1[NE * 32 * 16 * 32];     // stage0: IN=512, OUT=256
__device__ uint4 g_wf2[NE * 16 * 16 * 32];     // stage1: IN=256, OUT=256
__device__ uint4 g_wf3[NE * 16 * 32 * 32];     // stage2: IN=256, OUT=512

// ---------------- helpers ----------------
__device__ __forceinline__ uint32_t pack2(float a, float b) {
    __half2 h = __floats2half2_rn(a, b);
    return *(uint32_t*)&h;
}

__device__ __forceinline__ void mma16(float* c, const uint32_t* a,
                                      uint32_t b0, uint32_t b1) {
    asm volatile(
        "mma.sync.aligned.m16n8k16.row.col.f32.f16.f16.f32 "
        "{%0,%1,%2,%3}, {%4,%5,%6,%7}, {%8,%9}, {%0,%1,%2,%3};"
        : "+f"(c[0]), "+f"(c[1]), "+f"(c[2]), "+f"(c[3])
        : "r"(a[0]), "r"(a[1]), "r"(a[2]), "r"(a[3]), "r"(b0), "r"(b1));
}

__device__ __forceinline__ void cp16(uint32_t smem_dst, const void* gsrc) {
    asm volatile("cp.async.cg.shared.global [%0], [%1], 16;"
                 :: "r"(smem_dst), "l"(gsrc));
}

// ---------------- weight pre-transform (fp16 m16n8k16 B fragments) ----------------
template <int IN, int OUT>
__device__ __forceinline__ void prep_one(int idx, const float* W, uint4* WF) {
    constexpr int NTPP = OUT / 16;
    constexpr int GS   = IN / 16;
    int lane = idx & 31;
    int rest = idx >> 5;
    int ntp  = rest % NTPP;
    int gs   = (rest / NTPP) % GS;
    int e    = rest / (NTPP * GS);
    int n0 = ntp * 16 + (lane >> 2);
    int k0 = gs * 16 + (lane & 3) * 2;
    const float* We = W + (size_t)e * OUT * IN;
    uint4 v;
    v.x = pack2(We[(size_t)(n0 + 0) * IN + k0],     We[(size_t)(n0 + 0) * IN + k0 + 1]);
    v.y = pack2(We[(size_t)(n0 + 0) * IN + k0 + 8], We[(size_t)(n0 + 0) * IN + k0 + 9]);
    v.z = pack2(We[(size_t)(n0 + 8) * IN + k0],     We[(size_t)(n0 + 8) * IN + k0 + 1]);
    v.w = pack2(We[(size_t)(n0 + 8) * IN + k0 + 8], We[(size_t)(n0 + 8) * IN + k0 + 9]);
    WF[idx] = v;
}

// ---------------- mask dtype detection + counter zeroing ----------------
__global__ void detect_and_zero(const unsigned char* __restrict__ m) {
    __shared__ int bad;
    if (threadIdx.x == 0) bad = 0;
    if (threadIdx.x < 48) ((int*)g_cnt)[threadIdx.x] = 0;
    __syncthreads();
    int t = threadIdx.x;
    #pragma unroll
    for (int k = 0; k < NK; k++) {
        int s = 0;
        #pragma unroll
        for (int e = 0; e < NE; e++)
            s += (m[(e * NK + k) * T_TOK + t] != 0) ? 1 : 0;
        if (s != 1) bad = 1;
    }
    __syncthreads();
    if (threadIdx.x == 0) g_maskmode = bad ? 0 : 1;
}

// ---------------- fused pre-pass: route + prep + round_x ----------------
#define NROUTE  (3 * NK * T_TOK)
#define NPREP   (NE*32*16*32 + NE*16*16*32 + NE*16*32*32)
#define NRX     (T_TOK * 512 / 8)      // one uint4 (8 halves) per thread
#define PRE_THREADS (NROUTE + NPREP + NRX)

__global__ void pre_fused(const unsigned char* __restrict__ m1,
                          const unsigned char* __restrict__ m2,
                          const unsigned char* __restrict__ m3,
                          const float* __restrict__ r1,
                          const float* __restrict__ r2,
                          const float* __restrict__ r3,
                          const float* __restrict__ W1,
                          const float* __restrict__ W2,
                          const float* __restrict__ W3,
                          const float4* __restrict__ x) {
    int idx = blockIdx.x * blockDim.x + threadIdx.x;
    // ---- routing ----
    if (idx < NROUTE) {
        int s   = idx / (NK * T_TOK);
        int rem = idx % (NK * T_TOK);
        int k   = rem / T_TOK;
        int t   = rem % T_TOK;
        const unsigned char* m = (s == 0) ? m1 : (s == 1) ? m2 : m3;
        const float*         r = (s == 0) ? r1 : (s == 1) ? r2 : r3;
        int e = 0;
        if (g_maskmode) {
            #pragma unroll
            for (int i = 0; i < NE; i++)
                if (m[(i * NK + k) * T_TOK + t]) e = i;
        } else {
            const int* mi = (const int*)m;
            #pragma unroll
            for (int i = 0; i < NE; i++)
                if (mi[(i * NK + k) * T_TOK + t]) e = i;
        }
        float w = r[t * NK + k];
        int gg = k * NE + e;
        int p = atomicAdd(&g_cnt[s][gg], 1);
        g_tok[s][gg][p] = t;
        g_wgt[s][gg][p] = w;
        return;
    }
    idx -= NROUTE;
    // ---- weight prep ----
    if (idx < NPREP) {
        constexpr int N1 = NE * 32 * 16 * 32;
        constexpr int N2 = NE * 16 * 16 * 32;
        if (idx < N1)            { prep_one<512, 256>(idx, W1, g_wf1); }
        else if (idx < N1 + N2)  { prep_one<256, 256>(idx - N1, W2, g_wf2); }
        else                     { prep_one<256, 512>(idx - N1 - N2, W3, g_wf3); }
        return;
    }
    idx -= NPREP;
    // ---- round x to fp16 (one uint4 = 8 floats per thread) ----
    if (idx < NRX) {
        float4 v0 = x[2 * idx], v1 = x[2 * idx + 1];
        uint4 u = { pack2(v0.x, v0.y), pack2(v0.z, v0.w),
                    pack2(v1.x, v1.y), pack2(v1.z, v1.w) };
        ((uint4*)g_xr)[idx] = u;
    }
}

// ---------------- activation summing (fp16 partials -> fp16 packed) ----------------
__device__ __forceinline__ uint32_t h2sum(uint32_t ua, uint32_t ub) {
    float2 a = __half22float2(*(__half2*)&ua);
    float2 b = __half22float2(*(__half2*)&ub);
    return pack2(a.x + b.x, a.y + b.y);
}

__global__ void sum_round(const uint4* __restrict__ a, const uint4* __restrict__ b,
                          uint4* __restrict__ dst) {
    int i = blockIdx.x * blockDim.x + threadIdx.x;   // one uint4 (8 halves) per thread
    uint4 ua = a[i], ub = b[i];
    uint4 u = { h2sum(ua.x, ub.x), h2sum(ua.y, ub.y),
                h2sum(ua.z, ub.z), h2sum(ua.w, ub.w) };
    dst[i] = u;
}

// ---------------- fp16 mma.sync gathered expert GEMM ----------------
// BM=128, BN=128, BK=64 (4 k16 steps), 256 threads, 8 warps (2m x 4n), warp 64x32.
// A: pre-rounded fp16 via cp.async, 16B-XOR swizzle; B: cp.async fragment gmem.
// 3-deep pipeline, 1 sync/chunk. All stage partials stored packed fp16.
#define SMEM_TOTAL_BYTES 99328

template <int STAGE, int IN, int OUT>
__global__ __launch_bounds__(256, 2)
void moe_mma(const void* __restrict__ Ain,
             const float* __restrict__ Bias) {
    const uint4* WFg;
    uint32_t *O0, *O1;
    if constexpr (STAGE == 0)      { WFg = g_wf1; O0 = g_h1a; O1 = g_h1b; }
    else if constexpr (STAGE == 1) { WFg = g_wf2; O0 = g_h2a; O1 = g_h2b; }
    else                           { WFg = g_wf3; O0 = g_h3a; O1 = g_h3b; }
    constexpr bool RELU = (STAGE == 2);
    constexpr int NTPP = OUT / 16;
    constexpr int GS   = IN / 16;
    constexpr int NC   = IN / 64;

    const int g  = blockIdx.z;                 // slot*8 + expert
    const int n  = g_cnt[STAGE][g];
    const int m0 = blockIdx.x * 128;
    if (m0 >= n) return;
    const int e  = g & 7;
    const int n0 = blockIdx.y * 128;
    uint32_t* Out = (g >= 8) ? O1 : O0;

    extern __shared__ __align__(16) char dsm[];
    int*   s_tok = (int*)(dsm + 98304);
    float* s_w   = (float*)(dsm + 98816);

    const int tid  = threadIdx.x;
    const int wid  = tid >> 5;
    const int lane = tid & 31;
    const int wm   = wid >> 2;
    const int wn   = wid & 3;
    const int l2   = lane >> 2;
    const int l3   = lane & 3;

    if (tid < 128) {
        int gi  = m0 + tid;
        int src = (gi < n) ? gi : (n - 1);
        s_tok[tid] = g_tok[STAGE][g][src];
        s_w[tid]   = (gi < n) ? g_wgt[STAGE][g][src] : 0.0f;
    }
    __syncthreads();

    const uint4* WFe = WFg + (size_t)e * GS * NTPP * 32;
    const int ntp0 = blockIdx.y * 8;

    // A copy plan: rows (tid>>3)+{0,32,64,96}, 16B segment tid&7
    const int aseg = tid & 7;
    const int dseg = aseg ^ ((tid >> 3) & 7);
    const char* abase[4];
    uint32_t adst[4];
    uint32_t smA = (uint32_t)__cvta_generic_to_shared(dsm);
    #pragma unroll
    for (int i = 0; i < 4; i++) {
        int row = (tid >> 3) + i * 32;
        abase[i] = (const char*)Ain + ((size_t)s_tok[row] * IN + aseg * 8) * 2;
        adst[i]  = smA + row * 128 + dseg * 16;
    }
    uint32_t smB = (uint32_t)__cvta_generic_to_shared(dsm + 49152);

    auto ISSUE = [&](int ch, int buf) {
        #pragma unroll
        for (int i = 0; i < 4; i++)
            cp16(adst[i] + buf * 16384, abase[i] + ch * 128);
        #pragma unroll
        for (int i = 0; i < 4; i++) {
            int f  = tid + i * 256;           // [s4][ntp8][lane32]
            int bs = f >> 8;
            int bp = (f >> 5) & 7;
            int bl = f & 31;
            cp16(smB + buf * 16384 + f * 16,
                 WFe + ((size_t)(ch * 4 + bs) * NTPP + ntp0 + bp) * 32 + bl);
        }
        asm volatile("cp.async.commit_group;" ::: "memory");
    };

    float c[4][4][4];
    #pragma unroll
    for (int a = 0; a < 4; a++)
        #pragma unroll
        for (int b = 0; b < 4; b++)
            #pragma unroll
            for (int d = 0; d < 4; d++) c[a][b][d] = 0.0f;

    auto COMP = [&](int buf) {
        const char* Ab = dsm + buf * 16384;
        const uint4* Bb = (const uint4*)(dsm + 49152 + buf * 16384);
        #pragma unroll
        for (int s = 0; s < 4; s++) {
            const int off0 = (((2 * s)     ^ l2) << 4) + l3 * 4;
            const int off1 = (((2 * s + 1) ^ l2) << 4) + l3 * 4;
            uint32_t a[4][4];
            #pragma unroll
            for (int mi = 0; mi < 4; mi++) {
                const char* rp = Ab + (wm * 64 + mi * 16 + l2) * 128;
                a[mi][0] = *(const uint32_t*)(rp + off0);
                a[mi][1] = *(const uint32_t*)(rp + 1024 + off0);
                a[mi][2] = *(const uint32_t*)(rp + off1);
                a[mi][3] = *(const uint32_t*)(rp + 1024 + off1);
            }
            uint4 b0 = Bb[s * 256 + (wn * 2 + 0) * 32 + lane];
            uint4 b1 = Bb[s * 256 + (wn * 2 + 1) * 32 + lane];
            #pragma unroll
            for (int mi = 0; mi < 4; mi++) {
                mma16(c[mi][0], a[mi], b0.x, b0.y);
                mma16(c[mi][1], a[mi], b0.z, b0.w);
                mma16(c[mi][2], a[mi], b1.x, b1.y);
                mma16(c[mi][3], a[mi], b1.z, b1.w);
            }
        }
    };

    // 3-deep pipeline
    ISSUE(0, 0);
    ISSUE(1, 1);
    asm volatile("cp.async.wait_group 1;" ::: "memory");
    __syncthreads();
    int buf = 0;
    for (int ch = 0; ch < NC; ch++) {
        COMP(buf);
        if (ch + 2 < NC) {
            int nb = buf + 2; if (nb >= 3) nb -= 3;
            ISSUE(ch + 2, nb);
            asm volatile("cp.async.wait_group 1;" ::: "memory");
            __syncthreads();
        } else if (ch + 1 < NC) {
            asm volatile("cp.async.wait_group 0;" ::: "memory");
            __syncthreads();
        }
        if (++buf == 3) buf = 0;
    }

    // --- epilogue: bias (+relu) * routing weight, packed fp16 scatter by token ---
    float2 bias[4];
    #pragma unroll
    for (int nt = 0; nt < 4; nt++)
        bias[nt] = *(const float2*)&Bias[e * OUT + n0 + wn * 32 + nt * 8 + l3 * 2];

    #pragma unroll
    for (int mi = 0; mi < 4; mi++) {
        #pragma unroll
        for (int half = 0; half < 2; half++) {
            int r  = wm * 64 + mi * 16 + l2 + half * 8;
            int gi = m0 + r;
            if (gi >= n) continue;
            int   t = s_tok[r];
            float w = s_w[r];
            #pragma unroll
            for (int nt = 0; nt < 4; nt++) {
                size_t idx = (size_t)t * OUT + n0 + wn * 32 + nt * 8 + l3 * 2;
                float2 v;
                v.x = c[mi][nt][half * 2 + 0] + bias[nt].x;
                v.y = c[mi][nt][half * 2 + 1] + bias[nt].y;
                if constexpr (RELU) {
                    v.x = fmaxf(v.x, 0.0f);
                    v.y = fmaxf(v.y, 0.0f);
                }
                v.x *= w; v.y *= w;
                Out[idx >> 1] = pack2(v.x, v.y);
            }
        }
    }
}

// ---------------- final combine + relu (reads packed fp16 partials) ----------------
__global__ void finalize(float* __restrict__ out) {
    int i = blockIdx.x * blockDim.x + threadIdx.x;   // one uint4 (8 halves) per thread
    uint4 ua = ((const uint4*)g_h3a)[i];
    uint4 ub = ((const uint4*)g_h3b)[i];
    float4 o0, o1;
    {
        float2 a = __half22float2(*(__half2*)&ua.x), b = __half22float2(*(__half2*)&ub.x);
        o0.x = fmaxf(a.x + b.x, 0.0f); o0.y = fmaxf(a.y + b.y, 0.0f);
        a = __half22float2(*(__half2*)&ua.y); b = __half22float2(*(__half2*)&ub.y);
        o0.z = fmaxf(a.x + b.x, 0.0f); o0.w = fmaxf(a.y + b.y, 0.0f);
        a = __half22float2(*(__half2*)&ua.z); b = __half22float2(*(__half2*)&ub.z);
        o1.x = fmaxf(a.x + b.x, 0.0f); o1.y = fmaxf(a.y + b.y, 0.0f);
        a = __half22float2(*(__half2*)&ua.w); b = __half22float2(*(__half2*)&ub.w);
        o1.z = fmaxf(a.x + b.x, 0.0f); o1.w = fmaxf(a.y + b.y, 0.0f);
    }
    ((float4*)out)[2 * i]     = o0;
    ((float4*)out)[2 * i + 1] = o1;
}

// ---------------- launch ----------------
extern "C" void kernel_launch(void* const* d_in, const int* in_sizes, int n_in,
                              void* d_out, int out_size) {
    const float*         x  = (const float*)d_in[0];
    const unsigned char* m1 = (const unsigned char*)d_in[1];
    const unsigned char* m2 = (const unsigned char*)d_in[2];
    const unsigned char* m3 = (const unsigned char*)d_in[3];
    const float*         r1 = (const float*)d_in[4];
    const float*         r2 = (const float*)d_in[5];
    const float*         r3 = (const float*)d_in[6];
    const float*         W1 = (const float*)d_in[7];
    const float*         b1 = (const float*)d_in[8];
    const float*         W2 = (const float*)d_in[9];
    const float*         b2 = (const float*)d_in[10];
    const float*         W3 = (const float*)d_in[11];
    const float*         b3 = (const float*)d_in[12];
    float* out = (float*)d_out;

    void *xr, *h1a, *h1b, *h1s, *h2a, *h2b, *h2s;
    cudaGetSymbolAddress(&xr,  g_xr);
    cudaGetSymbolAddress(&h1a, g_h1a);
    cudaGetSymbolAddress(&h1b, g_h1b);
    cudaGetSymbolAddress(&h1s, g_h1s);
    cudaGetSymbolAddress(&h2a, g_h2a);
    cudaGetSymbolAddress(&h2b, g_h2b);
    cudaGetSymbolAddress(&h2s, g_h2s);

    static bool attr_done = false;
    if (!attr_done) {
        cudaFuncSetAttribute(moe_mma<0, 512, 256>,
                             cudaFuncAttributeMaxDynamicSharedMemorySize, SMEM_TOTAL_BYTES);
        cudaFuncSetAttribute(moe_mma<1, 256, 256>,
                             cudaFuncAttributeMaxDynamicSharedMemorySize, SMEM_TOTAL_BYTES);
        cudaFuncSetAttribute(moe_mma<2, 256, 512>,
                             cudaFuncAttributeMaxDynamicSharedMemorySize, SMEM_TOTAL_BYTES);
        attr_done = true;
    }

    detect_and_zero<<<1, 256>>>(m1);
    pre_fused<<<(PRE_THREADS + 255) / 256, 256>>>(m1, m2, m3, r1, r2, r3,
                                                  W1, W2, W3, (const float4*)x);

    dim3 g1(T_TOK / 128, 256 / 128, 16);
    dim3 g3(T_TOK / 128, 512 / 128, 16);

    moe_mma<0, 512, 256><<<g1, 256, SMEM_TOTAL_BYTES>>>(xr, b1);
    sum_round<<<(T_TOK * 256 / 8) / 256, 256>>>((const uint4*)h1a, (const uint4*)h1b, (uint4*)h1s);
    moe_mma<1, 256, 256><<<g1, 256, SMEM_TOTAL_BYTES>>>(h1s, b2);
    sum_round<<<(T_TOK * 256 / 8) / 256, 256>>>((const uint4*)h2a, (const uint4*)h2b, (uint4*)h2s);
    moe_mma<2, 256, 512><<<g3, 256, SMEM_TOTAL_BYTES>>>(h2s, b3);

    finalize<<<(T_TOK * 512 / 8) / 256, 256>>>(out);
}